// round 14
// baseline (speedup 1.0000x reference)
#include <cuda_runtime.h>
#include <cstdint>

#define NN     7680
#define NASM   256
#define CAPA   30
#define BATCH  64
#define KMAX   8
#define NTM    1024
#define NWARP  32
#define MAXC   960
#define S1BLK  960     // step1: 15 chunks x 64 samples
#define NN4    (NN / 4)
#define QCH    8       // colnorm source-chunk

// dynamic smem layout (bytes): [0,7680) cand/sc8 union, [7680,38400) sinvc,
// [38400,69120) srb
#define SMEM_DYN_BYTES (7680 + 30720 + 30720)

__device__ float         g_invc[NN];
__device__ unsigned char g_scores8[BATCH][NN];
__device__ unsigned int  g_rowbits[NN];

static __device__ __forceinline__ unsigned long long make_key(float v, int j){
    // v > 0. Bigger value -> bigger key; equal value -> smaller j wins.
    return (((unsigned long long)__float_as_uint(v)) << 32) | (unsigned int)(NN - 1 - j);
}
static __device__ __forceinline__ int key_j(unsigned long long k){
    return NN - 1 - (int)(k & 0xffffffffull);
}

// ---------------------------------------------------------------------------
// Fused prep (unchanged from R13 pass):
//  blocks [0,960):      step1 scores (uint8 exact counts), dedup by s[b]
//  blocks [960,1216):   colnorm + rowbits, gather-parallel
// ---------------------------------------------------------------------------
__global__ void __launch_bounds__(128) prep_kernel(
    const int* __restrict__ p, const int* __restrict__ s,
    const float* __restrict__ W_in, const float* __restrict__ W_rec)
{
    const int bid = blockIdx.x;
    const int tid = threadIdx.x;
    if (bid < S1BLK){
        __shared__ int ss[BATCH];
        const int b = bid / 15;
        if (tid < BATCH) ss[tid] = s[tid];
        __syncthreads();
        const int sb = ss[b];
        bool dup = false;
        for (int b2 = 0; b2 < b; ++b2) dup |= (ss[b2] == sb);
        if (dup) return;                              // representative writes instead

        const int c4 = (bid % 15) * 128 + tid;        // float4 index 0..1919
        const float4* src = (const float4*)(W_in + (size_t)sb * CAPA * NN) + c4;
        float ax = 0.f, ay = 0.f, az = 0.f, aw = 0.f;
        #pragma unroll 1
        for (int g = 0; g < 3; ++g){                  // 10 loads in flight per group
            float4 w[10];
            #pragma unroll
            for (int uu = 0; uu < 10; ++uu)
                w[uu] = __ldg(src + (size_t)(g * 10 + uu) * NN4);
            #pragma unroll
            for (int uu = 0; uu < 10; ++uu){          // integer counts: exact any order
                ax += w[uu].x; ay += w[uu].y; az += w[uu].z; aw += w[uu].w;
            }
        }
        uchar4 r;
        r.x = (unsigned char)(int)ax; r.y = (unsigned char)(int)ay;
        r.z = (unsigned char)(int)az; r.w = (unsigned char)(int)aw;
        ((uchar4*)g_scores8[b])[c4] = r;
    } else {
        // ---- colnorm + rowbits for destination assembly a ------------------
        __shared__ int      sp2[NASM];
        __shared__ int      qlist[NASM];
        __shared__ unsigned rbl[QCH * CAPA];
        __shared__ int      cnt[CAPA];
        __shared__ int      snq;
        const int a = bid - S1BLK;
        sp2[tid]       = p[tid];
        sp2[tid + 128] = p[tid + 128];
        if (tid < CAPA) cnt[tid] = 0;
        __syncthreads();
        if (tid < 32){                                // warp 0: sources pointing to a
            int run = 0;
            for (int g = 0; g < 8; ++g){
                bool m = (sp2[g * 32 + tid] == a);
                unsigned bal = __ballot_sync(0xffffffffu, m);
                if (m) qlist[run + __popc(bal & ((1u << tid) - 1u))] = g * 32 + tid;
                run += __popc(bal);
            }
            if (tid == 0) snq = run;
        }
        __syncthreads();
        const int nq = snq;
        for (int c0 = 0; c0 < nq; c0 += QCH){
            const int nqc   = min(QCH, nq - c0);
            const int tasks = nqc * CAPA;
            for (int i = tid; i < tasks; i += 128){
                int qi = i / CAPA, m = i % CAPA;
                int q  = qlist[c0 + qi];
                const float* row = W_rec + (size_t)(q * CAPA + m) * NN + a * CAPA;
                unsigned bits = 0;
                #pragma unroll
                for (int c = 0; c < CAPA; ++c)
                    if (row[c] != 0.f) bits |= (1u << c);
                rbl[i] = bits;
                g_rowbits[q * CAPA + m] = bits;
            }
            __syncthreads();
            if (tid < CAPA){
                int add = 0;
                for (int w = 0; w < tasks; ++w) add += (rbl[w] >> tid) & 1;
                cnt[tid] += add;
            }
            __syncthreads();
        }
        if (tid < CAPA) g_invc[a * CAPA + tid] = 1.0f / fmaxf((float)cnt[tid], 1e-6f);
    }
}

// ---------------------------------------------------------------------------
// Main: one block per sample; 1024 threads; 2 barriers per chase step.
// ---------------------------------------------------------------------------
__global__ void __launch_bounds__(NTM) pointer_ac_kernel(
    const int* __restrict__ p, const int* __restrict__ s,
    const int* __restrict__ k, float* __restrict__ out)
{
    extern __shared__ char dyn[];
    unsigned long long* cand = (unsigned long long*)dyn;      // [MAXC], chase phase
    unsigned char*      sc8  = (unsigned char*)dyn;           // [NN], kWTA phase (union)
    float*              sinvc = (float*)(dyn + 7680);         // [NN]
    unsigned int*       srb   = (unsigned int*)(dyn + 38400); // [NN]

    __shared__ int   warpHist[NWARP * 31];
    __shared__ int   hist[31];
    __shared__ int   sp[NASM];
    __shared__ int   ssamp[BATCH];
    __shared__ int   scnt[NASM];
    __shared__ int   sel[CAPA];
    __shared__ int   wtgt[NWARP][CAPA];               // per-warp Phase A slots
    __shared__ unsigned int wmask[NWARP][CAPA];
    __shared__ unsigned int warb[NWARP][CAPA];
    __shared__ int   warpSum[NWARP], warpOff[NWARP];
    __shared__ int   sT, sNG, sticket, sbesta;
    __shared__ int   sncand2[2];                      // parity double buffer

    const int b    = blockIdx.x;
    const int tid  = threadIdx.x;
    const int lane = tid & 31;
    const int wid  = tid >> 5;

    if (tid < NASM) sp[tid] = p[tid];
    if (tid < BATCH) ssamp[tid] = s[tid];
    const int kb = __ldg(&k[b]);
    if (tid < NWARP * 31) warpHist[tid] = 0;
    if (tid == 0){ sticket = 0; sncand2[0] = 0; sncand2[1] = 0; }

    #pragma unroll
    for (int r = 0; r < 2; ++r){                      // sinvc: 1920 float4
        int i = tid + r * NTM;
        if (i < NN4) ((float4*)sinvc)[i] = ((const float4*)g_invc)[i];
    }
    #pragma unroll
    for (int r = 0; r < 2; ++r){                      // srb: 1920 uint4
        int i = tid + r * NTM;
        if (i < NN4) ((uint4*)srb)[i] = ((const uint4*)g_rowbits)[i];
    }
    __syncthreads();

    // representative sample (first occurrence of s[b]) holds the scores
    int rep = b;
    for (int b2 = 0; b2 < BATCH; ++b2){
        if (ssamp[b2] == ssamp[b]){ rep = b2; break; }
    }
    if (tid < NN / 16)                                // sc8: 480 uint4 (byte array)
        ((uint4*)sc8)[tid] = ((const uint4*)g_scores8[rep])[tid];
    __syncthreads();

    // segment: first 512 threads get 8 bytes, rest 7 (ascending j order)
    const int seglen  = (tid < 512) ? 8 : 7;
    const int segbase = (tid < 512) ? tid * 8 : 4096 + (tid - 512) * 7;

    // ====== dense kWTA via histogram (exact ints 0..30) =====================
    {
        int* myh = warpHist + wid * 31;
        for (int i = 0; i < seglen; ++i){
            int v = sc8[segbase + i];
            atomicAdd(&myh[v], 1);
        }
        __syncthreads();
        if (tid < 31){
            int c = 0;
            #pragma unroll
            for (int w = 0; w < NWARP; ++w) c += warpHist[w * 31 + tid];
            hist[tid] = c;
        }
        __syncthreads();
        if (tid == 0){
            int suf = 0, T = 0, ng = 0;
            for (int v = 30; v >= 0; --v){
                suf += hist[v];
                if (suf >= CAPA){ T = v; ng = suf - hist[v]; break; }
            }
            sT = T; sNG = ng;
        }
        __syncthreads();
        const int T    = sT;
        const int ng   = sNG;
        const int need = CAPA - ng;

        int cntT = 0;
        for (int i = 0; i < seglen; ++i) cntT += (sc8[segbase + i] == T);
        int incl = cntT;
        #pragma unroll
        for (int o = 1; o < 32; o <<= 1){
            int n = __shfl_up_sync(0xffffffffu, incl, o);
            if (lane >= o) incl += n;
        }
        if (lane == 31) warpSum[wid] = incl;
        __syncthreads();
        if (tid == 0){
            int run = 0;
            #pragma unroll
            for (int w = 0; w < NWARP; ++w){ warpOff[w] = run; run += warpSum[w]; }
        }
        __syncthreads();
        int slotT = warpOff[wid] + incl - cntT;

        for (int i = 0; i < seglen; ++i){
            int j = segbase + i;
            int v = sc8[j];
            if (v > T){
                int sl = atomicAdd(&sticket, 1);      // set order irrelevant
                sel[sl] = j;
            } else if (v == T){
                if (slotT < need) sel[ng + slotT] = j;
                ++slotT;
            }
        }
        __syncthreads();
    }

    // ====== recurrent pointer-chase: 2 barriers per step ====================
    for (int t = 0; t < KMAX; ++t){
        if (t >= kb) break;                           // uniform per block

        // Phase A (every warp redundantly, own slots; no barrier needed)
        int an = (lane < CAPA) ? sel[lane] : 0;
        int tg = (lane < CAPA) ? sp[an / CAPA] : (256 + lane);
        unsigned mm = __match_any_sync(0xffffffffu, tg);
        if (lane < CAPA) warb[wid][lane] = srb[an];
        bool leader = (lane < CAPA) && ((int)(__ffs(mm) - 1) == lane);
        unsigned lb = __ballot_sync(0xffffffffu, leader);
        const int ntg = __popc(lb);
        if (leader){
            int pos = __popc(lb & ((1u << lane) - 1u));
            wtgt[wid][pos]  = tg;
            wmask[wid][pos] = mm;
        }

        // Phase B: warp wid handles target wid (ntg <= 30 < 32)
        if (wid < ntg){
            int a = wtgt[wid][wid];
            unsigned srcs = wmask[wid][wid];
            int j = a * CAPA + lane;
            float ic = (lane < CAPA) ? sinvc[j] : 0.f;
            float vv = 0.f;
            while (srcs){                             // m ascending: same FP order
                int m = __ffs(srcs) - 1; srcs &= srcs - 1;
                if ((warb[wid][m] >> lane) & 1u) vv += ic;
            }
            bool pos = (lane < CAPA) && (vv > 0.f);
            unsigned bal = __ballot_sync(0xffffffffu, pos);
            if (bal){
                int ldr = __ffs(bal) - 1;
                int base = 0;
                if (lane == ldr) base = atomicAdd(&sncand2[t & 1], __popc(bal));
                base = __shfl_sync(0xffffffffu, base, ldr);
                if (pos) cand[base + __popc(bal & ((1u << lane) - 1u))] = make_key(vv, j);
            }
        }
        __syncthreads();                              // BAR 1: cand/sncand complete

        // Phase C: rank-select top-30 (+ smallest-index zero fill)
        const int nc = sncand2[t & 1];
        for (int q = tid; q < nc; q += NTM){
            unsigned long long kq = cand[q];
            int rank = 0;
            for (int x = 0; x < nc; ++x) rank += (cand[x] > kq);
            if (rank < CAPA) sel[rank] = key_j(kq);
        }
        if (tid == 0){
            sncand2[(t + 1) & 1] = 0;                 // pre-zero next step's slot
            if (nc < CAPA){
                int P = nc, j = 0;
                while (P < CAPA){
                    bool ispos = false;
                    for (int x = 0; x < nc; ++x) ispos |= (key_j(cand[x]) == j);
                    if (!ispos) sel[P++] = j;
                    ++j;
                }
            }
        }
        __syncthreads();                              // BAR 2: sel ready
    }

    // ====== overlaps -> argmax (warp 0 reduce) -> one-hot ===================
    if (tid < NASM) scnt[tid] = 0;
    __syncthreads();
    if (tid < CAPA) atomicAdd(&scnt[sel[tid] / CAPA], 1);
    __syncthreads();
    if (wid == 0){
        unsigned long long bk = 0;
        #pragma unroll
        for (int r = 0; r < NASM / 32; ++r){
            int a = lane + r * 32;
            unsigned long long key =
                (((unsigned long long)scnt[a]) << 32) | (unsigned)(NASM - 1 - a);
            if (key > bk) bk = key;                   // max count, then smallest a
        }
        #pragma unroll
        for (int o = 16; o > 0; o >>= 1){
            unsigned long long obk = __shfl_xor_sync(0xffffffffu, bk, o);
            if (obk > bk) bk = obk;
        }
        if (lane == 0) sbesta = NASM - 1 - (int)(bk & 0xffffffffull);
    }
    __syncthreads();
    if (tid < NASM) out[(size_t)b * NASM + tid] = (tid == sbesta) ? 1.0f : 0.0f;
}

// ---------------------------------------------------------------------------
extern "C" void kernel_launch(void* const* d_in, const int* in_sizes, int n_in,
                              void* d_out, int out_size)
{
    const int*   p     = (const int*)d_in[0];     // [256]
    const int*   s     = (const int*)d_in[1];     // [64]
    const int*   k     = (const int*)d_in[2];     // [64]
    const float* W_in  = (const float*)d_in[3];   // [7680*7680]
    const float* W_rec = (const float*)d_in[4];   // [7680*7680]
    float*       out   = (float*)d_out;           // [64*256]

    cudaFuncSetAttribute(pointer_ac_kernel,
                         cudaFuncAttributeMaxDynamicSharedMemorySize, SMEM_DYN_BYTES);
    prep_kernel<<<S1BLK + NASM, 128>>>(p, s, W_in, W_rec);
    pointer_ac_kernel<<<BATCH, NTM, SMEM_DYN_BYTES>>>(p, s, k, out);
}